// round 17
// baseline (speedup 1.0000x reference)
#include <cuda_runtime.h>
#include <cuda_bf16.h>

#define N_NODES 50000
#define N_EDGES 800000
#define D_IN    128
#define HF      64
#define NB      196            // ceil(50000/256) for alloc
#define GB      782            // ceil(50000/64) gemm blocks (64 nodes/block)
#define EB      3125           // N_EDGES/256 exact
#define AGB     6250           // ceil(50000/8) agg blocks (warp = node)
#define GEMM_SMEM (2 * 64 * 132 * 4)   // sWt + sfeat, 67.6KB

// Static scratch (allocation is forbidden)
__device__ float g_ft[N_NODES * HF];
__device__ int   g_count[N_NODES];     // zero-init; k_alloc re-zeroes each replay
__device__ int   g_off[N_NODES];
__device__ int   g_cnt[N_NODES];
__device__ int   g_cursor[N_NODES];
__device__ int   g_srcs[N_EDGES];
__device__ int   g_total;

// Packed fp32x2 FMA (Blackwell FFMA2, PTX-only)
#define FMA2(acc, a, b) \
    asm("fma.rn.f32x2 %0, %1, %2, %0;" : "+l"(acc) : "l"(a), "l"(b))

__device__ __forceinline__ float hsum(unsigned long long v) {
    float a, b; asm("mov.b64 {%0,%1}, %2;" : "=f"(a), "=f"(b) : "l"(v));
    return a + b;
}

// ---------------------------------------------------------------------------
// K1: ft = feat @ W ([N,128]@[128,64]); R13 staged 4x4 register tile,
// 64 nodes/block (measured best of 4 gemm variants). Histogram un-fused
// (runs concurrently on the side stream).
// ---------------------------------------------------------------------------
__global__ __launch_bounds__(256) void k_gemm(const float* __restrict__ feat,
                                              const float* __restrict__ W) {
    extern __shared__ float sm[];
    float* sWt = sm;                 // [64][132]
    float* sft = sm + 64 * 132;      // [64][132]

    int tid = threadIdx.x;
    for (int idx = tid; idx < D_IN * HF; idx += 256) {
        int k = idx >> 6, c = idx & 63;
        sWt[c * 132 + k] = W[idx];
    }
    int node0 = blockIdx.x * 64;
    const float4* fv = (const float4*)feat;
    float4* sf4 = (float4*)sft;
    for (int idx = tid; idx < 64 * 32; idx += 256) {
        int r = idx >> 5, s = idx & 31;
        int n = node0 + r;
        sf4[r * 33 + s] = (n < N_NODES) ? fv[(size_t)n * 32 + s]
                                        : make_float4(0.f, 0.f, 0.f, 0.f);
    }
    __syncthreads();

    int cg = tid & 15, ng = tid >> 4;
    const ulonglong2* wb = (const ulonglong2*)sWt;
    const ulonglong2* ab = (const ulonglong2*)sft;
    int wo[4], ao[4];
    #pragma unroll
    for (int i = 0; i < 4; i++) wo[i] = (cg + 16 * i) * 33;
    #pragma unroll
    for (int r = 0; r < 4; r++) ao[r] = (4 * ng + r) * 33;

    unsigned long long acc[4][4];
    #pragma unroll
    for (int i = 0; i < 4; i++)
        #pragma unroll
        for (int r = 0; r < 4; r++) acc[i][r] = 0ull;

    #pragma unroll 2
    for (int k = 0; k < 32; k++) {                     // 32 chunks x 4 = K=128
        ulonglong2 w[4], a[4];
        #pragma unroll
        for (int i = 0; i < 4; i++) w[i] = wb[wo[i] + k];
        #pragma unroll
        for (int r = 0; r < 4; r++) a[r] = ab[ao[r] + k];
        #pragma unroll
        for (int i = 0; i < 4; i++)
            #pragma unroll
            for (int r = 0; r < 4; r++) {
                FMA2(acc[i][r], a[r].x, w[i].x);
                FMA2(acc[i][r], a[r].y, w[i].y);
            }
    }

    #pragma unroll
    for (int r = 0; r < 4; r++) {
        int n = node0 + 4 * ng + r;
        if (n < N_NODES) {
            #pragma unroll
            for (int i = 0; i < 4; i++)
                g_ft[n * 64 + cg + 16 * i] = hsum(acc[i][r]);
        }
    }
}

// ---------------------------------------------------------------------------
// Side-stream chain: histogram -> alloc -> place (independent of gemm)
// ---------------------------------------------------------------------------
__global__ void k_hist(const int* __restrict__ dst) {
    int e = blockIdx.x * 256 + threadIdx.x;            // exact grid
    if (e == 0) g_total = 0;
    atomicAdd(&g_count[dst[e]], 1);
}

__global__ void k_alloc() {
    int i = blockIdx.x * 256 + threadIdx.x;
    if (i < N_NODES) {
        int cnt = g_count[i];
        g_count[i] = 0;                                // restore replay invariant
        int off = atomicAdd(&g_total, cnt);
        g_off[i]    = off;
        g_cnt[i]    = cnt;
        g_cursor[i] = off;
    }
}

__global__ void k_place(const int* __restrict__ src, const int* __restrict__ dst) {
    int e = blockIdx.x * 256 + threadIdx.x;            // exact grid
    int pos = atomicAdd(&g_cursor[dst[e]], 1);
    g_srcs[pos] = src[e];
}

// ---------------------------------------------------------------------------
// K4: fused score + softmax + aggregate. ONE WARP PER NODE. (R13 verbatim,
// measured 34.0us.) 32 lanes = 2 edges x 16 lanes; lane j owns float4 #j.
// out[d] = (sum_e exp(e)*ft[src_e]) / sum_e exp(e)   (max-shift cancels)
// ---------------------------------------------------------------------------
__global__ __launch_bounds__(256) void k_agg(float* __restrict__ out) {
    const unsigned FULL = 0xffffffffu;
    int warp = (blockIdx.x * 256 + threadIdx.x) >> 5;  // node id
    if (warp >= N_NODES) return;
    int lane = threadIdx.x & 31;
    int j    = lane & 15;
    int e    = lane >> 4;

    const float4* __restrict__ ftv = (const float4*)g_ft;
    float4 b = ftv[warp * 16 + j];

    int beg = g_off[warp], cnt = g_cnt[warp];
    float4 acc = make_float4(0.f, 0.f, 0.f, 0.f);
    float den = 0.f;

#define EDGEF(A) do {                                                 \
        float p = (A).x * b.x + (A).y * b.y + (A).z * b.z + (A).w * b.w; \
        p += __shfl_xor_sync(FULL, p, 1);                             \
        p += __shfl_xor_sync(FULL, p, 2);                             \
        float ex = __expf(p * 0.25f);                                 \
        acc.x += ex * (A).x; acc.y += ex * (A).y;                     \
        acc.z += ex * (A).z; acc.w += ex * (A).w;                     \
        den += ex;                                                    \
    } while (0)

    for (int k0 = 0; k0 < cnt; k0 += 32) {
        int lim = cnt - k0; if (lim > 32) lim = 32;
        int myidx = (lane < lim) ? g_srcs[beg + k0 + lane] : 0;
        int npair = lim >> 1;

        int t = 0;
        for (; t + 4 <= npair; t += 4) {
            int s0 = __shfl_sync(FULL, myidx, 2 * t + e);
            int s1 = __shfl_sync(FULL, myidx, 2 * t + 2 + e);
            int s2 = __shfl_sync(FULL, myidx, 2 * t + 4 + e);
            int s3 = __shfl_sync(FULL, myidx, 2 * t + 6 + e);
            float4 a0 = ftv[s0 * 16 + j];
            float4 a1 = ftv[s1 * 16 + j];
            float4 a2 = ftv[s2 * 16 + j];
            float4 a3 = ftv[s3 * 16 + j];
            EDGEF(a0); EDGEF(a1); EDGEF(a2); EDGEF(a3);
        }
        for (; t < npair; ++t) {
            int s0 = __shfl_sync(FULL, myidx, 2 * t + e);
            float4 a0 = ftv[s0 * 16 + j];
            EDGEF(a0);
        }
        if (lim & 1) {
            int s0 = __shfl_sync(FULL, myidx, lim - 1);
            float4 a0 = ftv[s0 * 16 + j];
            float p = a0.x * b.x + a0.y * b.y + a0.z * b.z + a0.w * b.w;
            p += __shfl_xor_sync(FULL, p, 1);
            p += __shfl_xor_sync(FULL, p, 2);
            float ex = (e == 0) ? __expf(p * 0.25f) : 0.f;
            acc.x += ex * a0.x; acc.y += ex * a0.y;
            acc.z += ex * a0.z; acc.w += ex * a0.w;
            den += ex;
        }
    }
#undef EDGEF

    acc.x += __shfl_xor_sync(FULL, acc.x, 16);
    acc.y += __shfl_xor_sync(FULL, acc.y, 16);
    acc.z += __shfl_xor_sync(FULL, acc.z, 16);
    acc.w += __shfl_xor_sync(FULL, acc.w, 16);
    den   += __shfl_xor_sync(FULL, den,   16);

    if (lane < 16) {
        float inv = (den > 0.f) ? (1.f / den) : 0.f;
        ((float4*)out)[warp * 16 + j] =
            make_float4(acc.x * inv, acc.y * inv, acc.z * inv, acc.w * inv);
    }
}

// ---------------------------------------------------------------------------
// Stream/event plumbing for the two-branch graph. Created once at program
// static-init (host-side resources only; no device allocation; kernel_launch
// itself has no guards and does identical work every call).
// ---------------------------------------------------------------------------
struct HxStreams {
    cudaStream_t s2;
    cudaEvent_t  fork_ev, join_ev;
    HxStreams() {
        cudaStreamCreateWithFlags(&s2, cudaStreamNonBlocking);
        cudaEventCreateWithFlags(&fork_ev, cudaEventDisableTiming);
        cudaEventCreateWithFlags(&join_ev, cudaEventDisableTiming);
    }
};
static HxStreams hx;

extern "C" void kernel_launch(void* const* d_in, const int* in_sizes, int n_in,
                              void* d_out, int out_size) {
    const float* feat = (const float*)d_in[0];
    const float* W    = (const float*)d_in[1];
    const int*   src  = (const int*)d_in[2];
    const int*   dst  = (const int*)d_in[3];
    float* out = (float*)d_out;

    cudaFuncSetAttribute(k_gemm, cudaFuncAttributeMaxDynamicSharedMemorySize,
                         GEMM_SMEM);

    // Fork: CSR chain on side stream, gemm on the main (captured) stream.
    cudaEventRecord(hx.fork_ev, 0);
    cudaStreamWaitEvent(hx.s2, hx.fork_ev, 0);

    k_hist <<<EB, 256, 0, hx.s2>>>(dst);
    k_alloc<<<NB, 256, 0, hx.s2>>>();
    k_place<<<EB, 256, 0, hx.s2>>>(src, dst);
    cudaEventRecord(hx.join_ev, hx.s2);

    k_gemm<<<GB, 256, GEMM_SMEM>>>(feat, W);           // concurrent with CSR

    // Join, then aggregate.
    cudaStreamWaitEvent(0, hx.join_ev, 0);
    k_agg<<<AGB, 256>>>(out);
}